// round 17
// baseline (speedup 1.0000x reference)
#include <cuda_runtime.h>
#include <cuda_bf16.h>
#include <cstdint>

#define EPSF 1e-8f
static constexpr int B_  = 8;
static constexpr int N_  = 256;
static constexpr int NF_ = 2048;

__device__ __nv_bfloat16 g_K[B_ * N_ * N_];   // bf16 K, L2-resident
__device__ float g_rsK[B_ * N_];              // rowsum(K)
__device__ float g_cpr[B_ * N_];              // raw coupling: Σ_j K_ij sin(...)

#define GRIDDEP_WAIT() asm volatile("griddepcontrol.wait;" ::: "memory")

// ---------------------------------------------------------------------------
// helpers
// ---------------------------------------------------------------------------
__device__ __forceinline__ void unpack8(uint4 kr, float* f)
{
    float2 f0 = __bfloat1622float2(*reinterpret_cast<__nv_bfloat162*>(&kr.x));
    float2 f1 = __bfloat1622float2(*reinterpret_cast<__nv_bfloat162*>(&kr.y));
    float2 f2 = __bfloat1622float2(*reinterpret_cast<__nv_bfloat162*>(&kr.z));
    float2 f3 = __bfloat1622float2(*reinterpret_cast<__nv_bfloat162*>(&kr.w));
    f[0] = f0.x; f[1] = f0.y; f[2] = f1.x; f[3] = f1.y;
    f[4] = f2.x; f[5] = f2.y; f[6] = f3.x; f[7] = f3.y;
}

__device__ __forceinline__ float dot8(uint4 kr, const float* vj)
{
    float kf[8];
    unpack8(kr, kf);
    float acc = 0.f;
#pragma unroll
    for (int x = 0; x < 8; ++x) acc = fmaf(kf[x], vj[x], acc);
    return acc;
}

// 256-thread broadcast sum (fixed order -> deterministic across CTAs)
__device__ __forceinline__ float blk_sum256(float val, float* red)
{
#pragma unroll
    for (int o = 16; o; o >>= 1) val += __shfl_xor_sync(0xffffffffu, val, o);
    if ((threadIdx.x & 31) == 0) red[threadIdx.x >> 5] = val;
    __syncthreads();
    if (threadIdx.x < 32) {
        float s = (threadIdx.x < 8) ? red[threadIdx.x] : 0.f;
#pragma unroll
        for (int o = 4; o; o >>= 1) s += __shfl_xor_sync(0xffffffffu, s, o);
        if (threadIdx.x == 0) red[8] = s;
    }
    __syncthreads();
    float r = red[8];
    __syncthreads();
    return r;
}

// ---------------------------------------------------------------------------
// Kernel 1: pooling -> K row (bf16) + per-row scalars (rsK, raw coupling).
// NO atomics, NO state needing reset. Grid (256,8), 256 thr, <=32 regs.
// ---------------------------------------------------------------------------
__global__ void __launch_bounds__(256, 8) pool_build_k(
    const float* __restrict__ A,
    const float* __restrict__ theta_g, const float* __restrict__ alpha_g)
{
    const int I = blockIdx.x, b = blockIdx.y;
    const int t = threadIdx.x;
    const int wd = t >> 5, lane = t & 31;
    const float* base = A + ((size_t)b * NF_ + (size_t)I * 8) * NF_;

    float thmine = theta_g[b * N_ + t];
    float alp    = __ldg(&alpha_g[(size_t)I * N_ + t]);

    __shared__ float rA[9], rC[9], rD[9];
    __shared__ float stI;
    if (t == I) stI = thmine;                       // broadcast theta_I

    // direct block-column accumulation: cols [8t, 8t+8) over 8 rows
    const float4* rp = reinterpret_cast<const float4*>(base) + 2 * t;
    float acc0 = 0.f, acc1 = 0.f;
#pragma unroll
    for (int r = 0; r < 8; ++r) {
        float4 f0 = __ldcs(rp + (size_t)r * 512);
        float4 f1 = __ldcs(rp + (size_t)r * 512 + 1);
        acc0 += (f0.x + f0.y) + (f0.z + f0.w);
        acc1 += (f1.x + f1.y) + (f1.z + f1.w);
    }
    float w = fmaxf((acc0 + acc1) * (1.0f / 64.0f), 0.0f);   // relu(A_lat[I,t])

    // ---- round 1: sum w ----
    {
        float sv = w;
#pragma unroll
        for (int o = 16; o; o >>= 1) sv += __shfl_xor_sync(0xffffffffu, sv, o);
        if (lane == 0) rA[wd] = sv;
    }
    __syncthreads();
    if (t < 32) {
        float s = (t < 8) ? rA[t] : 0.f;
#pragma unroll
        for (int o = 4; o; o >>= 1) s += __shfl_xor_sync(0xffffffffu, s, o);
        if (t == 0) rA[8] = s;
    }
    __syncthreads();
    const float rowsum = rA[8];
    const float tI = stI;

    float W = (rowsum > EPSF) ? (w / (rowsum + EPSF)) : (1.0f / N_);
    float x  = W + EPSF;
    float x2 = x * x, x4 = x2 * x2, x8 = x4 * x4;
    __nv_bfloat16 kb = __float2bfloat16(x8 * x2);   // K = x^10 (bf16)
    g_K[((size_t)b * N_ + I) * N_ + t] = kb;

    float kf = __bfloat162float(kb);
    float sn = kf * __sinf(thmine - tI - alp);      // K_It * sin(th_t - th_I - a_It)

    // ---- round 2: (sum K, sum sin-term) ----
    {
        float sv = kf, cv = sn;
#pragma unroll
        for (int o = 16; o; o >>= 1) {
            sv += __shfl_xor_sync(0xffffffffu, sv, o);
            cv += __shfl_xor_sync(0xffffffffu, cv, o);
        }
        if (lane == 0) { rC[wd] = sv; rD[wd] = cv; }
    }
    __syncthreads();
    if (t == 0) {
        float rsK = 0.f, cps = 0.f;
#pragma unroll
        for (int i = 0; i < 8; ++i) { rsK += rC[i]; cps += rD[i]; }
        g_rsK[b * N_ + I] = rsK;
        g_cpr[b * N_ + I] = cps;
    }
}

// ---------------------------------------------------------------------------
// Kernel 2 (kfuse): the ONLY tail node. Grid (8,8) = 64 CTAs, 256 thr, PDL.
// Each CTA of batch b redundantly + deterministically computes:
//  prolog (overlaps pool): softmax p, own-column output scalars
//  post-wait: u1/u2 from rsK; row fixed-point check; S (fixed-order block sum);
//  FULL column certificate (thread t: column pair, row half);
//  -> all 8 CTAs reach the same decision with no communication.
// Fast path: write own 32 outputs. Fallback: faithful 10-iter Sinkhorn,
// write own 32 outputs. No atomics, no globals to reset.
// ---------------------------------------------------------------------------
__global__ void __launch_bounds__(256) kfuse(
    const float* __restrict__ theta_g, const float* __restrict__ gamma_g,
    const float* __restrict__ omega_g, const float* __restrict__ alpha_g,
    const float* __restrict__ logk_g,  float* __restrict__ out)
{
    __shared__ float p_s[256];
    __shared__ float u1_s[256];
    __shared__ float u2_s[256];
    __shared__ float red[10];
    __shared__ float part[2][128][2];
    __shared__ int   flag;
    __shared__ float vsh[256], tsh[256], kv_s[256];   // fallback only

    const int g = blockIdx.x, b = blockIdx.y;
    const int t = threadIdx.x;
    const int j = g * 32 + (t & 31);                  // own output node (t<32)

    // ---- prolog: pure-input work (overlaps pool under PDL) ----
    float e = expf(gamma_g[b * N_ + t]);              // no-max softmax
    float ti = 0.f, ga = 0.f, om = 0.f, kap = 0.f;
    if (t < 32) {
        ti  = theta_g[b * N_ + j];
        ga  = gamma_g[b * N_ + j];
        om  = omega_g[j];
        kap = log1pf(expf(logk_g[j]));                // softplus
    }
    if (t == 0) flag = 0;
    float esum = blk_sum256(e, red);
    p_s[t] = e / esum;

    GRIDDEP_WAIT();                                   // wait for pool (PDL)

    // ---- pointwise Sinkhorn closed form (identical in every CTA) ----
    const float q  = 1.0f / N_;
    const float v1 = q / EPSF;                        // uniform v1 (certified below)
    float rsK = g_rsK[b * N_ + t];
    float u1  = p_s[t] / (rsK * q + EPSF);            // true first u (Kv0 = rsK/256)
    float kv1 = v1 * rsK;
    float u2  = p_s[t] / (kv1 + EPSF);
    u1_s[t] = u1;
    u2_s[t] = u2;
    float S = blk_sum256(u2 * kv1, red);              // fixed order
    if (u2 != u1) flag = 1;                           // row fixed-point check

    // ---- FULL column certificate: thread t -> cols (2c, 2c+1), rows half h ----
    {
        const uint32_t* kb32 = reinterpret_cast<const uint32_t*>(g_K + (size_t)b * N_ * N_);
        const int c = t & 127;                        // column pair index
        const int h = t >> 7;                         // row half
        float a0 = 0.f, a1 = 0.f;
#pragma unroll 8
        for (int k = 0; k < 128; ++k) {
            int i = h * 128 + k;
            uint32_t kk = __ldg(kb32 + (size_t)i * 128 + c);
            float2 f = __bfloat1622float2(*reinterpret_cast<__nv_bfloat162*>(&kk));
            float u = u1_s[i];
            a0 = fmaf(f.x, u, a0);
            a1 = fmaf(f.y, u, a1);
        }
        part[h][c][0] = a0;
        part[h][c][1] = a1;
    }
    __syncthreads();
    if (t < 128) {
        float k0 = part[0][t][0] + part[1][t][0];     // fixed order: half0 + half1
        float k1 = part[0][t][1] + part[1][t][1];
        if (!(k0 + EPSF == EPSF) || !(k1 + EPSF == EPSF)) flag = 1;
    }
    __syncthreads();

    if (flag == 0) {
        // -------- proven fixed point: write own 32 outputs --------
        if (t < 32) {
            float Sinv = 1.0f / (S + EPSF);
            float cp   = v1 * g_cpr[b * N_ + j];
            out[b * N_ + j] = ti + om + u2_s[j] * Sinv * cp + kap * (ga - ti);
        }
        return;
    }

    // -------- fallback: faithful 10-iter Sinkhorn from scratch --------
    // (deterministic; all 8 CTAs compute the same solution, each writes its
    //  own 32 outputs)
    {
        const int wd = t >> 5, lane = t & 31;
        float fti = theta_g[b * N_ + t];
        u1_s[t] = 1.0f / N_;                          // u
        vsh[t]  = 1.0f / N_;                          // v
        tsh[t]  = fti;
        __syncthreads();

        for (int it = 0; it < 10; ++it) {
            // u-update: 8 warps x 32 rows, K from L2
#pragma unroll 1
            for (int k = 0; k < 32; ++k) {
                int ii = wd * 32 + k;
                uint4 kr = reinterpret_cast<const uint4*>(g_K + ((size_t)b * N_ + ii) * N_)[lane];
                float acc = dot8(kr, &vsh[lane * 8]);
#pragma unroll
                for (int o = 16; o; o >>= 1) acc += __shfl_xor_sync(0xffffffffu, acc, o);
                if (lane == 0) u1_s[ii] = p_s[ii] / (acc + EPSF);
            }
            __syncthreads();
            // v-update: thread t = column j
            float s = 0.f;
#pragma unroll 1
            for (int ii = 0; ii < N_; ++ii)
                s = fmaf(__bfloat162float(g_K[((size_t)b * N_ + ii) * N_ + t]), u1_s[ii], s);
            __syncthreads();
            vsh[t] = (1.0f / N_) / (s + EPSF);
            __syncthreads();
        }

        // final Kv, S
#pragma unroll 1
        for (int k = 0; k < 32; ++k) {
            int ii = wd * 32 + k;
            uint4 kr = reinterpret_cast<const uint4*>(g_K + ((size_t)b * N_ + ii) * N_)[lane];
            float acc = dot8(kr, &vsh[lane * 8]);
#pragma unroll
            for (int o = 16; o; o >>= 1) acc += __shfl_xor_sync(0xffffffffu, acc, o);
            if (lane == 0) kv_s[ii] = acc;
        }
        __syncthreads();
        float Sf = blk_sum256(u1_s[t] * kv_s[t], red);
        float Sinv = 1.0f / (Sf + EPSF);

        // coupling for every row t; store only own range
        float cacc = 0.f;
#pragma unroll 1
        for (int jj = 0; jj < N_; ++jj) {
            float kv = __bfloat162float(g_K[((size_t)b * N_ + t) * N_ + jj]) * vsh[jj];
            float d  = tsh[jj] - fti - alpha_g[(size_t)t * N_ + jj];
            cacc = fmaf(kv, __sinf(d), cacc);
        }
        if (wd == g) {
            float fga  = gamma_g[b * N_ + t];
            float fom  = omega_g[t];
            float fkap = log1pf(expf(logk_g[t]));
            float td = fom + u1_s[t] * Sinv * cacc + fkap * (fga - fti);
            out[b * N_ + t] = fti + td;
        }
    }
}

// ---------------------------------------------------------------------------
extern "C" void kernel_launch(void* const* d_in, const int* in_sizes, int n_in,
                              void* d_out, int out_size)
{
    const float* theta = (const float*)d_in[0];
    const float* gamma = (const float*)d_in[1];
    const float* A     = (const float*)d_in[2];
    const float* omega = (const float*)d_in[3];
    const float* alpha = (const float*)d_in[4];
    const float* logk  = (const float*)d_in[5];
    float* out = (float*)d_out;

    dim3 g1(256, 8);
    pool_build_k<<<g1, 256>>>(A, theta, alpha);

    // single tail node with PDL: prolog overlaps pool
    {
        cudaLaunchConfig_t cfg = {};
        cfg.gridDim  = dim3(8, 8);
        cfg.blockDim = dim3(256);
        cudaLaunchAttribute at[1];
        at[0].id = cudaLaunchAttributeProgrammaticStreamSerialization;
        at[0].val.programmaticStreamSerializationAllowed = 1;
        cfg.attrs = at;
        cfg.numAttrs = 1;
        cudaLaunchKernelEx(&cfg, kfuse, theta, gamma, omega, alpha, logk, out);
    }
}